// round 15
// baseline (speedup 1.0000x reference)
#include <cuda_runtime.h>
#include <cuda_bf16.h>
#include <cstdint>

#define DH 256
#define NLEAF 16384

// ---------------- helpers ----------------
__device__ __forceinline__ uint32_t smem_u32(const void* p) {
    uint32_t a;
    asm("{ .reg .u64 t; cvta.to.shared.u64 t, %1; cvt.u32.u64 %0, t; }" : "=r"(a) : "l"(p));
    return a;
}
__device__ __forceinline__ void cp16(uint32_t dst, const void* src) {
    asm volatile("cp.async.cg.shared.global [%0], [%1], 16;" :: "r"(dst), "l"(src));
}
__device__ __forceinline__ void cpcommit() { asm volatile("cp.async.commit_group;" ::: "memory"); }
template <int N> __device__ __forceinline__ void cpwait() {
    asm volatile("cp.async.wait_group %0;" :: "n"(N) : "memory");
}
__device__ __forceinline__ float sigf(float x) { return 1.0f / (1.0f + __expf(-x)); }

// pack fp32 -> (hi bf16 <<16) | (lo bf16): exact two-term split
__device__ __forceinline__ uint32_t packhl(float x) {
    __nv_bfloat16 h = __float2bfloat16(x);
    __nv_bfloat16 l = __float2bfloat16(x - __bfloat162float(h));
    uint16_t hb = *reinterpret_cast<uint16_t*>(&h), lb = *reinterpret_cast<uint16_t*>(&l);
    return ((uint32_t)hb << 16) | lb;
}
__device__ __forceinline__ float unpackhl(uint32_t p) {
    uint16_t hb = (uint16_t)(p >> 16), lb = (uint16_t)(p & 0xffff);
    __nv_bfloat16 h = *reinterpret_cast<__nv_bfloat16*>(&hb);
    __nv_bfloat16 l = *reinterpret_cast<__nv_bfloat16*>(&lb);
    return __bfloat162float(h) + __bfloat162float(l);
}
// bf16x2 words (elem k low half, k+1 high half)
__device__ __forceinline__ uint32_t pair_hi(float w0, float w1) {
    __nv_bfloat16 h0 = __float2bfloat16(w0), h1 = __float2bfloat16(w1);
    return (uint32_t)*reinterpret_cast<uint16_t*>(&h0) |
           ((uint32_t)*reinterpret_cast<uint16_t*>(&h1) << 16);
}
__device__ __forceinline__ uint32_t pair_lo(float w0, float w1) {
    __nv_bfloat16 h0 = __float2bfloat16(w0), h1 = __float2bfloat16(w1);
    float l0 = w0 - __bfloat162float(h0), l1 = w1 - __bfloat162float(h1);
    return pair_hi(l0, l1);
}
// D += A*B (m16n8k16 bf16 -> fp32)
__device__ __forceinline__ void mma16816(float* d, const uint32_t* a, uint32_t b0, uint32_t b1) {
    asm volatile("mma.sync.aligned.m16n8k16.row.col.f32.bf16.bf16.f32 "
        "{%0,%1,%2,%3}, {%4,%5,%6,%7}, {%8,%9}, {%0,%1,%2,%3};"
        : "+f"(d[0]), "+f"(d[1]), "+f"(d[2]), "+f"(d[3])
        : "r"(a[0]), "r"(a[1]), "r"(a[2]), "r"(a[3]), "r"(b0), "r"(b1));
}

// ---------------- scratch ----------------
__device__ float g_cA[NLEAF * DH];
__device__ float g_cB[(NLEAF / 2) * DH];
__device__ float g_cl[(NLEAF / 2) * DH];
__device__ __align__(16) uint32_t g_hpA[NLEAF * DH];        // packed h (hi|lo)
__device__ __align__(16) uint32_t g_hpB[(NLEAF / 2) * DH];
__device__ __align__(16) uint32_t g_hlp[(NLEAF / 2) * DH];
__device__ __align__(16) uint32_t g_xp[NLEAF * 320];        // packed emb gather (K pad 320)
__device__ __align__(16) uint32_t g_Bc[2][3 * 256 * 256];   // [hi/lo][g][n][kp] kp0..127=Wc,128..255=Ws
__device__ __align__(16) uint32_t g_Bx[2][3 * 256 * 160];   // leaf weights, kp 0..159 (K pad 320)

// ---------------- prep kernels ----------------
__global__ void prep_wc(const float* __restrict__ Wc, const float* __restrict__ Ws) {
    int e = blockIdx.x * 256 + threadIdx.x;           // 3*256*256
    int kp = e & 255, n = (e >> 8) & 255, g = e >> 16;
    const float* W = (kp < 128) ? Wc : Ws;
    int k = (kp & 127) * 2;
    float w0 = W[(size_t)k * 768 + g * 256 + n];
    float w1 = W[(size_t)(k + 1) * 768 + g * 256 + n];
    g_Bc[0][e] = pair_hi(w0, w1);
    g_Bc[1][e] = pair_lo(w0, w1);
}
__global__ void prep_wx(const float* __restrict__ Wx) {
    int e = blockIdx.x * 256 + threadIdx.x;           // 3*256*160
    int kp = e % 160, n = (e / 160) & 255, g = e / (160 * 256);
    int k = kp * 2;
    float w0 = (k < 300) ? Wx[(size_t)k * 768 + g * 256 + n] : 0.f;
    float w1 = (k + 1 < 300) ? Wx[(size_t)(k + 1) * 768 + g * 256 + n] : 0.f;
    g_Bx[0][e] = pair_hi(w0, w1);
    g_Bx[1][e] = pair_lo(w0, w1);
}
__global__ void prep_emb(const int* __restrict__ ids, const float* __restrict__ emb) {
    int e = blockIdx.x * 256 + threadIdx.x;           // 16384*320
    int k = e % 320, i = e / 320;
    float x = (k < 300) ? emb[(size_t)ids[i] * 300 + k] : 0.f;
    g_xp[e] = packhl(x);
}

// =====================================================================
// Tensor kernel. MODE 0=leaf (NG=3,K=320), 1=comb1 (NG=2,K=256),
// 2=comb2 (NG=3,K=512 over [h_odd ; hl]). Block 128 rows x 64 u.
// cp.async double-buffered; A packed (hi|lo) per element; B prepacked pairs.
// =====================================================================
#define APITCH 68
#define BPITCH 36
template <int MODE>
__global__ void __launch_bounds__(256, 1)
tree_mma(int src, const float* __restrict__ b0v, const float* __restrict__ b1v)
{
    constexpr int NG = (MODE == 1) ? 2 : 3;
    constexpr int NC = (MODE == 0) ? 5 : ((MODE == 1) ? 4 : 8);
    constexpr int A_BUF = 128 * APITCH;
    constexpr int B_HL = NG * 64 * BPITCH;
    constexpr int B_BUF = 2 * B_HL;
    constexpr int BOFF = 2 * A_BUF;
    constexpr int BIASOFF = BOFF + 2 * B_BUF;

    extern __shared__ uint32_t sm[];
    const uint32_t smb = smem_u32(sm);

    const int tid = threadIdx.x, lane = tid & 31, wid = tid >> 5;
    const int wm = wid & 3, wn = wid >> 2;
    const int g8 = lane >> 2, tig = lane & 3;
    const int m0 = blockIdx.x * 128, u0 = blockIdx.y * 64;

    float* sbias = (float*)(sm + BIASOFF);
    if (tid < NG * 64) {
        int col = (MODE == 1 ? 256 : 0) + (tid >> 6) * 256 + u0 + (tid & 63);
        float b = b0v[col];
        if (MODE) b += b1v[col];
        sbias[tid] = b;
    }

    const uint32_t* __restrict__ hp_in = src ? g_hpB : g_hpA;
    const float* __restrict__ c_in = src ? g_cB : g_cA;
    uint32_t* __restrict__ hp_out = src ? g_hpA : g_hpB;
    float* __restrict__ c_out = src ? g_cA : g_cB;

    float acc[NG][2][4][4];
#pragma unroll
    for (int g = 0; g < NG; g++)
#pragma unroll
        for (int mt = 0; mt < 2; mt++)
#pragma unroll
            for (int nt = 0; nt < 4; nt++)
#pragma unroll
                for (int e = 0; e < 4; e++) acc[g][mt][nt][e] = 0.f;

    auto stage = [&](int buf, int c) {
        // A: 128 rows x 64 words -> 16 cp16 per row
#pragma unroll
        for (int i = 0; i < 8; i++) {
            int id = tid + i * 256;
            int r = id >> 4, q = id & 15;
            const uint32_t* srcp;
            if (MODE == 0)      srcp = g_xp + (size_t)(m0 + r) * 320 + c * 64 + q * 4;
            else if (MODE == 1) srcp = hp_in + (size_t)(2 * (m0 + r)) * DH + c * 64 + q * 4;
            else srcp = (c < 4) ? hp_in + (size_t)(2 * (m0 + r) + 1) * DH + c * 64 + q * 4
                                : g_hlp + (size_t)(m0 + r) * DH + (c - 4) * 64 + q * 4;
            cp16(smb + (buf * A_BUF + r * APITCH + q * 4) * 4, srcp);
        }
        // B: per h/l half: NG gates x 64 n x 32 words -> 8 cp16 per n
#pragma unroll
        for (int hl = 0; hl < 2; hl++) {
            const uint32_t* gB = (MODE == 0) ? g_Bx[hl] : g_Bc[hl];
#pragma unroll
            for (int i = 0; i < NG * 2; i++) {
                int id = tid + i * 256;
                int q = id & 7, n = (id >> 3) & 63, g = id >> 9;
                int gg = (MODE == 1) ? g + 1 : g;
                const uint32_t* srcp = gB + (size_t)(gg * 256 + u0 + n) * (MODE == 0 ? 160 : 256)
                                       + c * 32 + q * 4;
                cp16(smb + (BOFF + buf * B_BUF + hl * B_HL + g * (64 * BPITCH) + n * BPITCH + q * 4) * 4,
                     srcp);
            }
        }
        cpcommit();
    };

    auto compute = [&](int buf) {
        const uint32_t* Ab = sm + buf * A_BUF;
        const uint32_t* Bb = sm + BOFF + buf * B_BUF;
#pragma unroll
        for (int s = 0; s < 4; s++) {
            const int k0 = s * 16 + tig * 2;
            uint32_t aH[2][4], aL[2][4];
#pragma unroll
            for (int mt = 0; mt < 2; mt++) {
                const uint32_t* Ar = Ab + (wm * 32 + mt * 16 + g8) * APITCH;
                uint2 p00 = *(const uint2*)(Ar + k0);
                uint2 p01 = *(const uint2*)(Ar + k0 + 8);
                uint2 p10 = *(const uint2*)(Ar + 8 * APITCH + k0);
                uint2 p11 = *(const uint2*)(Ar + 8 * APITCH + k0 + 8);
                aH[mt][0] = __byte_perm(p00.x, p00.y, 0x7632); aL[mt][0] = __byte_perm(p00.x, p00.y, 0x5410);
                aH[mt][1] = __byte_perm(p10.x, p10.y, 0x7632); aL[mt][1] = __byte_perm(p10.x, p10.y, 0x5410);
                aH[mt][2] = __byte_perm(p01.x, p01.y, 0x7632); aL[mt][2] = __byte_perm(p01.x, p01.y, 0x5410);
                aH[mt][3] = __byte_perm(p11.x, p11.y, 0x7632); aL[mt][3] = __byte_perm(p11.x, p11.y, 0x5410);
            }
            const int kp0 = s * 8 + tig;
#pragma unroll
            for (int g = 0; g < NG; g++) {
#pragma unroll
                for (int nt = 0; nt < 4; nt++) {
                    const uint32_t* Bh = Bb + g * (64 * BPITCH) + (wn * 32 + nt * 8 + g8) * BPITCH;
                    uint32_t bH0 = Bh[kp0], bH1 = Bh[kp0 + 4];
                    uint32_t bL0 = Bh[B_HL + kp0], bL1 = Bh[B_HL + kp0 + 4];
#pragma unroll
                    for (int mt = 0; mt < 2; mt++) {
                        mma16816(acc[g][mt][nt], aH[mt], bH0, bH1);
                        mma16816(acc[g][mt][nt], aH[mt], bL0, bL1);
                        mma16816(acc[g][mt][nt], aL[mt], bH0, bH1);
                    }
                }
            }
        }
    };

    stage(0, 0);
    for (int c = 0; c < NC; c++) {
        if (c + 1 < NC) { stage((c + 1) & 1, c + 1); cpwait<1>(); }
        else cpwait<0>();
        __syncthreads();
        compute(c & 1);
        __syncthreads();
    }

    // ---- fused epilogue ----
#pragma unroll
    for (int mt = 0; mt < 2; mt++) {
        int rowb = m0 + wm * 32 + mt * 16 + g8;
#pragma unroll
        for (int nt = 0; nt < 4; nt++) {
            int nl = wn * 32 + nt * 8 + tig * 2;
            int u = u0 + nl;
#pragma unroll
            for (int half = 0; half < 2; half++) {
                int r = rowb + half * 8;
                int e = half * 2;
                float a0x = acc[0][mt][nt][e], a0y = acc[0][mt][nt][e + 1];
                float a1x = acc[1][mt][nt][e], a1y = acc[1][mt][nt][e + 1];
                if (MODE == 0) {
                    float gix = a0x + sbias[nl],      giy = a0y + sbias[nl + 1];
                    float gox = a1x + sbias[64 + nl], goy = a1y + sbias[64 + nl + 1];
                    float cpx = acc[2][mt][nt][e] + sbias[128 + nl];
                    float cpy = acc[2][mt][nt][e + 1] + sbias[128 + nl + 1];
                    float cx = sigf(gix) * tanhf(cpx), cy = sigf(giy) * tanhf(cpy);
                    float hx = sigf(gox) * tanhf(cx),  hy = sigf(goy) * tanhf(cy);
                    *(float2*)&g_cA[(size_t)r * DH + u] = make_float2(cx, cy);
                    uint2 hp = make_uint2(packhl(hx), packhl(hy));
                    *(uint2*)&g_hpA[(size_t)r * DH + u] = hp;
                } else if (MODE == 1) {
                    float gcx = a0x + sbias[nl],      gcy = a0y + sbias[nl + 1];
                    float gox = a1x + sbias[64 + nl], goy = a1y + sbias[64 + nl + 1];
                    float2 cc = *(const float2*)&c_in[(size_t)(2 * r) * DH + u];
                    float clx = sigf(gcx) * cc.x, cly = sigf(gcy) * cc.y;
                    float hlx = sigf(gox) * tanhf(clx), hly = sigf(goy) * tanhf(cly);
                    *(float2*)&g_cl[(size_t)r * DH + u] = make_float2(clx, cly);
                    uint2 hp = make_uint2(packhl(hlx), packhl(hly));
                    *(uint2*)&g_hlp[(size_t)r * DH + u] = hp;
                } else {
                    float gsx = a0x + sbias[nl],      gsy = a0y + sbias[nl + 1];
                    float gcx = a1x + sbias[64 + nl], gcy = a1y + sbias[64 + nl + 1];
                    float gox = acc[2][mt][nt][e] + sbias[128 + nl];
                    float goy = acc[2][mt][nt][e + 1] + sbias[128 + nl + 1];
                    float2 co = *(const float2*)&c_in[(size_t)(2 * r + 1) * DH + u];
                    float2 cs = *(const float2*)&g_cl[(size_t)r * DH + u];
                    float cnx = sigf(gcx) * co.x + sigf(gsx) * cs.x;
                    float cny = sigf(gcy) * co.y + sigf(gsy) * cs.y;
                    float hnx = sigf(gox) * tanhf(cnx), hny = sigf(goy) * tanhf(cny);
                    *(float2*)&c_out[(size_t)r * DH + u] = make_float2(cnx, cny);
                    uint2 hp = make_uint2(packhl(hnx), packhl(hny));
                    *(uint2*)&hp_out[(size_t)r * DH + u] = hp;
                }
            }
        }
    }
}

// =====================================================================
// Small levels (Mout < 128): block per node, thread = hidden unit.
// h states packed (reconstructed hi+lo); exact fp32 GEMV against W.
// =====================================================================
__global__ void __launch_bounds__(256, 1)
comb_small(int src, int stage, const float* __restrict__ Wc, const float* __restrict__ Ws,
           const float* __restrict__ bc, const float* __restrict__ bs,
           float* __restrict__ root_out)
{
    __shared__ float sh[512];
    const int node = blockIdx.x, tid = threadIdx.x;
    const uint32_t* __restrict__ hp_in = src ? g_hpB : g_hpA;
    const float* __restrict__ c_in = src ? g_cB : g_cA;
    uint32_t* __restrict__ hp_out = src ? g_hpA : g_hpB;
    float* __restrict__ c_out = src ? g_cA : g_cB;

    if (stage == 1) {
        sh[tid] = unpackhl(hp_in[(size_t)(2 * node) * DH + tid]);
        __syncthreads();
        float gc = bc[256 + tid] + bs[256 + tid];
        float go = bc[512 + tid] + bs[512 + tid];
#pragma unroll 8
        for (int k = 0; k < DH; k++) {
            float h = sh[k];
            gc += h * Wc[(size_t)k * 768 + 256 + tid];
            go += h * Wc[(size_t)k * 768 + 512 + tid];
        }
        float cl = sigf(gc) * c_in[(size_t)(2 * node) * DH + tid];
        float hl = sigf(go) * tanhf(cl);
        g_cl[(size_t)node * DH + tid] = cl;
        if (root_out) root_out[tid] = hl;
        else g_hlp[(size_t)node * DH + tid] = packhl(hl);
    } else {
        sh[tid] = unpackhl(hp_in[(size_t)(2 * node + 1) * DH + tid]);
        sh[256 + tid] = unpackhl(g_hlp[(size_t)node * DH + tid]);
        __syncthreads();
        float gs = bc[tid] + bs[tid];
        float gc = bc[256 + tid] + bs[256 + tid];
        float go = bc[512 + tid] + bs[512 + tid];
#pragma unroll 4
        for (int k = 0; k < DH; k++) {
            float ho = sh[k], hs = sh[256 + k];
            gs += ho * Wc[(size_t)k * 768 + tid]       + hs * Ws[(size_t)k * 768 + tid];
            gc += ho * Wc[(size_t)k * 768 + 256 + tid] + hs * Ws[(size_t)k * 768 + 256 + tid];
            go += ho * Wc[(size_t)k * 768 + 512 + tid] + hs * Ws[(size_t)k * 768 + 512 + tid];
        }
        float cn = sigf(gc) * c_in[(size_t)(2 * node + 1) * DH + tid] +
                   sigf(gs) * g_cl[(size_t)node * DH + tid];
        float hn = sigf(go) * tanhf(cn);
        c_out[(size_t)node * DH + tid] = cn;
        hp_out[(size_t)node * DH + tid] = packhl(hn);
    }
}

// =====================================================================
extern "C" void kernel_launch(void* const* d_in, const int* in_sizes, int n_in,
                              void* d_out, int out_size)
{
    const int*   ids = (const int*)d_in[0];
    const float* emb = (const float*)d_in[1];
    const float* Wx  = (const float*)d_in[2];
    const float* bx  = (const float*)d_in[3];
    const float* Ws  = (const float*)d_in[4];
    const float* bs  = (const float*)d_in[5];
    const float* Wc  = (const float*)d_in[6];
    const float* bc  = (const float*)d_in[7];
    float* out = (float*)d_out;
    (void)in_sizes; (void)n_in; (void)out_size;

    // dynamic smem sizes (bytes)
    const int SM3 = (2 * 128 * APITCH + 2 * 2 * 3 * 64 * BPITCH + 192) * 4;  // MODE 0/2
    const int SM2 = (2 * 128 * APITCH + 2 * 2 * 2 * 64 * BPITCH + 128) * 4;  // MODE 1
    cudaFuncSetAttribute(tree_mma<0>, cudaFuncAttributeMaxDynamicSharedMemorySize, SM3);
    cudaFuncSetAttribute(tree_mma<1>, cudaFuncAttributeMaxDynamicSharedMemorySize, SM2);
    cudaFuncSetAttribute(tree_mma<2>, cudaFuncAttributeMaxDynamicSharedMemorySize, SM3);

    prep_wc<<<768, 256>>>(Wc, Ws);
    prep_wx<<<480, 256>>>(Wx);
    prep_emb<<<NLEAF * 320 / 256, 256>>>(ids, emb);

    // leaf
    tree_mma<0><<<dim3(NLEAF / 128, 4), 256, SM3>>>(0, bx, nullptr);

    int M = NLEAF;
    for (int l = 0; l < 14; l++) {
        int Mo = M >> 1;
        int src = l & 1;   // 0: read A / write B ; 1: read B / write A
        if (Mo >= 128) {
            dim3 grid(Mo / 128, 4);
            tree_mma<1><<<grid, 256, SM2>>>(src, bc, bs);
            tree_mma<2><<<grid, 256, SM3>>>(src, bc, bs);
        } else {
            comb_small<<<Mo, 256>>>(src, 1, Wc, Ws, bc, bs, nullptr);
            comb_small<<<Mo, 256>>>(src, 2, Wc, Ws, bc, bs, nullptr);
        }
        M = Mo;
    }
    // root: sibling = zeros -> stage-1 math; level-14 state is in A buffers
    comb_small<<<1, 256>>>(0, 1, Wc, Ws, bc, bs, out);
}

// round 16
// speedup vs baseline: 1.0051x; 1.0051x over previous
#include <cuda_runtime.h>
#include <cuda_bf16.h>
#include <cstdint>

#define DH 256
#define NLEAF 16384

// ---------------- helpers ----------------
__device__ __forceinline__ uint32_t smem_u32(const void* p) {
    uint32_t a;
    asm("{ .reg .u64 t; cvta.to.shared.u64 t, %1; cvt.u32.u64 %0, t; }" : "=r"(a) : "l"(p));
    return a;
}
__device__ __forceinline__ void cp16(uint32_t dst, const void* src) {
    asm volatile("cp.async.cg.shared.global [%0], [%1], 16;" :: "r"(dst), "l"(src));
}
__device__ __forceinline__ void cpcommit() { asm volatile("cp.async.commit_group;" ::: "memory"); }
template <int N> __device__ __forceinline__ void cpwait() {
    asm volatile("cp.async.wait_group %0;" :: "n"(N) : "memory");
}
__device__ __forceinline__ float sigf(float x) { return 1.0f / (1.0f + __expf(-x)); }

// pack fp32 -> (hi bf16 <<16) | (lo bf16): exact two-term split
__device__ __forceinline__ uint32_t packhl(float x) {
    __nv_bfloat16 h = __float2bfloat16(x);
    __nv_bfloat16 l = __float2bfloat16(x - __bfloat162float(h));
    uint16_t hb = *reinterpret_cast<uint16_t*>(&h), lb = *reinterpret_cast<uint16_t*>(&l);
    return ((uint32_t)hb << 16) | lb;
}
__device__ __forceinline__ float unpackhl(uint32_t p) {
    uint16_t hb = (uint16_t)(p >> 16), lb = (uint16_t)(p & 0xffff);
    __nv_bfloat16 h = *reinterpret_cast<__nv_bfloat16*>(&hb);
    __nv_bfloat16 l = *reinterpret_cast<__nv_bfloat16*>(&lb);
    return __bfloat162float(h) + __bfloat162float(l);
}
// bf16x2 words (elem k low half, k+1 high half)
__device__ __forceinline__ uint32_t pair_hi(float w0, float w1) {
    __nv_bfloat16 h0 = __float2bfloat16(w0), h1 = __float2bfloat16(w1);
    return (uint32_t)*reinterpret_cast<uint16_t*>(&h0) |
           ((uint32_t)*reinterpret_cast<uint16_t*>(&h1) << 16);
}
__device__ __forceinline__ uint32_t pair_lo(float w0, float w1) {
    __nv_bfloat16 h0 = __float2bfloat16(w0), h1 = __float2bfloat16(w1);
    float l0 = w0 - __bfloat162float(h0), l1 = w1 - __bfloat162float(h1);
    return pair_hi(l0, l1);
}
// D += A*B (m16n8k16 bf16 -> fp32)
__device__ __forceinline__ void mma16816(float* d, const uint32_t* a, uint32_t b0, uint32_t b1) {
    asm volatile("mma.sync.aligned.m16n8k16.row.col.f32.bf16.bf16.f32 "
        "{%0,%1,%2,%3}, {%4,%5,%6,%7}, {%8,%9}, {%0,%1,%2,%3};"
        : "+f"(d[0]), "+f"(d[1]), "+f"(d[2]), "+f"(d[3])
        : "r"(a[0]), "r"(a[1]), "r"(a[2]), "r"(a[3]), "r"(b0), "r"(b1));
}

// ---------------- scratch ----------------
__device__ float g_cA[NLEAF * DH];
__device__ float g_cB[(NLEAF / 2) * DH];
__device__ float g_cl[(NLEAF / 2) * DH];
__device__ __align__(16) uint32_t g_hpA[NLEAF * DH];        // packed h (hi|lo)
__device__ __align__(16) uint32_t g_hpB[(NLEAF / 2) * DH];
__device__ __align__(16) uint32_t g_hlp[(NLEAF / 2) * DH];
__device__ __align__(16) uint32_t g_xp[NLEAF * 320];        // packed emb gather (K pad 320)
__device__ __align__(16) uint32_t g_Bc[2][3 * 256 * 256];   // [hi/lo][g][n][kp] kp0..127=Wc,128..255=Ws
__device__ __align__(16) uint32_t g_Bx[2][3 * 256 * 160];   // leaf weights, kp 0..159 (K pad 320)

// ---------------- prep kernels ----------------
__global__ void prep_wc(const float* __restrict__ Wc, const float* __restrict__ Ws) {
    int e = blockIdx.x * 256 + threadIdx.x;           // 3*256*256
    int kp = e & 255, n = (e >> 8) & 255, g = e >> 16;
    const float* W = (kp < 128) ? Wc : Ws;
    int k = (kp & 127) * 2;
    float w0 = W[(size_t)k * 768 + g * 256 + n];
    float w1 = W[(size_t)(k + 1) * 768 + g * 256 + n];
    g_Bc[0][e] = pair_hi(w0, w1);
    g_Bc[1][e] = pair_lo(w0, w1);
}
__global__ void prep_wx(const float* __restrict__ Wx) {
    int e = blockIdx.x * 256 + threadIdx.x;           // 3*256*160
    int kp = e % 160, n = (e / 160) & 255, g = e / (160 * 256);
    int k = kp * 2;
    float w0 = (k < 300) ? Wx[(size_t)k * 768 + g * 256 + n] : 0.f;
    float w1 = (k + 1 < 300) ? Wx[(size_t)(k + 1) * 768 + g * 256 + n] : 0.f;
    g_Bx[0][e] = pair_hi(w0, w1);
    g_Bx[1][e] = pair_lo(w0, w1);
}
__global__ void prep_emb(const int* __restrict__ ids, const float* __restrict__ emb) {
    int e = blockIdx.x * 256 + threadIdx.x;           // 16384*320
    int k = e % 320, i = e / 320;
    float x = (k < 300) ? emb[(size_t)ids[i] * 300 + k] : 0.f;
    g_xp[e] = packhl(x);
}

// =====================================================================
// Tensor kernel. MODE 0=leaf (NG=3,K=320), 1=comb1 (NG=2,K=256),
// 2=comb2 (NG=3,K=512 over [h_odd ; hl]). Block 128 rows x 64 u.
// cp.async double-buffered; A packed (hi|lo) per element; B prepacked pairs.
// =====================================================================
#define APITCH 68
#define BPITCH 36
template <int MODE>
__global__ void __launch_bounds__(256, 1)
tree_mma(int src, const float* __restrict__ b0v, const float* __restrict__ b1v)
{
    constexpr int NG = (MODE == 1) ? 2 : 3;
    constexpr int NC = (MODE == 0) ? 5 : ((MODE == 1) ? 4 : 8);
    constexpr int A_BUF = 128 * APITCH;
    constexpr int B_HL = NG * 64 * BPITCH;
    constexpr int B_BUF = 2 * B_HL;
    constexpr int BOFF = 2 * A_BUF;
    constexpr int BIASOFF = BOFF + 2 * B_BUF;

    extern __shared__ uint32_t sm[];
    const uint32_t smb = smem_u32(sm);

    const int tid = threadIdx.x, lane = tid & 31, wid = tid >> 5;
    const int wm = wid & 3, wn = wid >> 2;
    const int g8 = lane >> 2, tig = lane & 3;
    const int m0 = blockIdx.x * 128, u0 = blockIdx.y * 64;

    float* sbias = (float*)(sm + BIASOFF);
    if (tid < NG * 64) {
        int col = (MODE == 1 ? 256 : 0) + (tid >> 6) * 256 + u0 + (tid & 63);
        float b = b0v[col];
        if (MODE) b += b1v[col];
        sbias[tid] = b;
    }

    const uint32_t* __restrict__ hp_in = src ? g_hpB : g_hpA;
    const float* __restrict__ c_in = src ? g_cB : g_cA;
    uint32_t* __restrict__ hp_out = src ? g_hpA : g_hpB;
    float* __restrict__ c_out = src ? g_cA : g_cB;

    float acc[NG][2][4][4];
#pragma unroll
    for (int g = 0; g < NG; g++)
#pragma unroll
        for (int mt = 0; mt < 2; mt++)
#pragma unroll
            for (int nt = 0; nt < 4; nt++)
#pragma unroll
                for (int e = 0; e < 4; e++) acc[g][mt][nt][e] = 0.f;

    auto stage = [&](int buf, int c) {
        // A: 128 rows x 64 words -> 16 cp16 per row
#pragma unroll
        for (int i = 0; i < 8; i++) {
            int id = tid + i * 256;
            int r = id >> 4, q = id & 15;
            const uint32_t* srcp;
            if (MODE == 0)      srcp = g_xp + (size_t)(m0 + r) * 320 + c * 64 + q * 4;
            else if (MODE == 1) srcp = hp_in + (size_t)(2 * (m0 + r)) * DH + c * 64 + q * 4;
            else srcp = (c < 4) ? hp_in + (size_t)(2 * (m0 + r) + 1) * DH + c * 64 + q * 4
                                : g_hlp + (size_t)(m0 + r) * DH + (c - 4) * 64 + q * 4;
            cp16(smb + (buf * A_BUF + r * APITCH + q * 4) * 4, srcp);
        }
        // B: per h/l half: NG gates x 64 n x 32 words -> 8 cp16 per n
#pragma unroll
        for (int hl = 0; hl < 2; hl++) {
            const uint32_t* gB = (MODE == 0) ? g_Bx[hl] : g_Bc[hl];
#pragma unroll
            for (int i = 0; i < NG * 2; i++) {
                int id = tid + i * 256;
                int q = id & 7, n = (id >> 3) & 63, g = id >> 9;
                int gg = (MODE == 1) ? g + 1 : g;
                const uint32_t* srcp = gB + (size_t)(gg * 256 + u0 + n) * (MODE == 0 ? 160 : 256)
                                       + c * 32 + q * 4;
                cp16(smb + (BOFF + buf * B_BUF + hl * B_HL + g * (64 * BPITCH) + n * BPITCH + q * 4) * 4,
                     srcp);
            }
        }
        cpcommit();
    };

    auto compute = [&](int buf) {
        const uint32_t* Ab = sm + buf * A_BUF;
        const uint32_t* Bb = sm + BOFF + buf * B_BUF;
#pragma unroll
        for (int s = 0; s < 4; s++) {
            const int k0 = s * 16 + tig * 2;
            uint32_t aH[2][4], aL[2][4];
#pragma unroll
            for (int mt = 0; mt < 2; mt++) {
                const uint32_t* Ar = Ab + (wm * 32 + mt * 16 + g8) * APITCH;
                uint2 p00 = *(const uint2*)(Ar + k0);
                uint2 p01 = *(const uint2*)(Ar + k0 + 8);
                uint2 p10 = *(const uint2*)(Ar + 8 * APITCH + k0);
                uint2 p11 = *(const uint2*)(Ar + 8 * APITCH + k0 + 8);
                aH[mt][0] = __byte_perm(p00.x, p00.y, 0x7632); aL[mt][0] = __byte_perm(p00.x, p00.y, 0x5410);
                aH[mt][1] = __byte_perm(p10.x, p10.y, 0x7632); aL[mt][1] = __byte_perm(p10.x, p10.y, 0x5410);
                aH[mt][2] = __byte_perm(p01.x, p01.y, 0x7632); aL[mt][2] = __byte_perm(p01.x, p01.y, 0x5410);
                aH[mt][3] = __byte_perm(p11.x, p11.y, 0x7632); aL[mt][3] = __byte_perm(p11.x, p11.y, 0x5410);
            }
            const int kp0 = s * 8 + tig;
#pragma unroll
            for (int g = 0; g < NG; g++) {
#pragma unroll
                for (int nt = 0; nt < 4; nt++) {
                    const uint32_t* Bh = Bb + g * (64 * BPITCH) + (wn * 32 + nt * 8 + g8) * BPITCH;
                    uint32_t bH0 = Bh[kp0], bH1 = Bh[kp0 + 4];
                    uint32_t bL0 = Bh[B_HL + kp0], bL1 = Bh[B_HL + kp0 + 4];
#pragma unroll
                    for (int mt = 0; mt < 2; mt++) {
                        mma16816(acc[g][mt][nt], aH[mt], bH0, bH1);
                        mma16816(acc[g][mt][nt], aH[mt], bL0, bL1);
                        mma16816(acc[g][mt][nt], aL[mt], bH0, bH1);
                    }
                }
            }
        }
    };

    stage(0, 0);
    for (int c = 0; c < NC; c++) {
        if (c + 1 < NC) { stage((c + 1) & 1, c + 1); cpwait<1>(); }
        else cpwait<0>();
        __syncthreads();
        compute(c & 1);
        __syncthreads();
    }

    // ---- fused epilogue ----
#pragma unroll
    for (int mt = 0; mt < 2; mt++) {
        int rowb = m0 + wm * 32 + mt * 16 + g8;
#pragma unroll
        for (int nt = 0; nt < 4; nt++) {
            int nl = wn * 32 + nt * 8 + tig * 2;
            int u = u0 + nl;
#pragma unroll
            for (int half = 0; half < 2; half++) {
                int r = rowb + half * 8;
                int e = half * 2;
                float a0x = acc[0][mt][nt][e], a0y = acc[0][mt][nt][e + 1];
                float a1x = acc[1][mt][nt][e], a1y = acc[1][mt][nt][e + 1];
                if (MODE == 0) {
                    float gix = a0x + sbias[nl],      giy = a0y + sbias[nl + 1];
                    float gox = a1x + sbias[64 + nl], goy = a1y + sbias[64 + nl + 1];
                    float cpx = acc[2][mt][nt][e] + sbias[128 + nl];
                    float cpy = acc[2][mt][nt][e + 1] + sbias[128 + nl + 1];
                    float cx = sigf(gix) * tanhf(cpx), cy = sigf(giy) * tanhf(cpy);
                    float hx = sigf(gox) * tanhf(cx),  hy = sigf(goy) * tanhf(cy);
                    *(float2*)&g_cA[(size_t)r * DH + u] = make_float2(cx, cy);
                    uint2 hp = make_uint2(packhl(hx), packhl(hy));
                    *(uint2*)&g_hpA[(size_t)r * DH + u] = hp;
                } else if (MODE == 1) {
                    float gcx = a0x + sbias[nl],      gcy = a0y + sbias[nl + 1];
                    float gox = a1x + sbias[64 + nl], goy = a1y + sbias[64 + nl + 1];
                    float2 cc = *(const float2*)&c_in[(size_t)(2 * r) * DH + u];
                    float clx = sigf(gcx) * cc.x, cly = sigf(gcy) * cc.y;
                    float hlx = sigf(gox) * tanhf(clx), hly = sigf(goy) * tanhf(cly);
                    *(float2*)&g_cl[(size_t)r * DH + u] = make_float2(clx, cly);
                    uint2 hp = make_uint2(packhl(hlx), packhl(hly));
                    *(uint2*)&g_hlp[(size_t)r * DH + u] = hp;
                } else {
                    float gsx = a0x + sbias[nl],      gsy = a0y + sbias[nl + 1];
                    float gcx = a1x + sbias[64 + nl], gcy = a1y + sbias[64 + nl + 1];
                    float gox = acc[2][mt][nt][e] + sbias[128 + nl];
                    float goy = acc[2][mt][nt][e + 1] + sbias[128 + nl + 1];
                    float2 co = *(const float2*)&c_in[(size_t)(2 * r + 1) * DH + u];
                    float2 cs = *(const float2*)&g_cl[(size_t)r * DH + u];
                    float cnx = sigf(gcx) * co.x + sigf(gsx) * cs.x;
                    float cny = sigf(gcy) * co.y + sigf(gsy) * cs.y;
                    float hnx = sigf(gox) * tanhf(cnx), hny = sigf(goy) * tanhf(cny);
                    *(float2*)&c_out[(size_t)r * DH + u] = make_float2(cnx, cny);
                    uint2 hp = make_uint2(packhl(hnx), packhl(hny));
                    *(uint2*)&hp_out[(size_t)r * DH + u] = hp;
                }
            }
        }
    }
}

// =====================================================================
// Small levels (Mout < 128): block per node, thread = hidden unit.
// h states packed (reconstructed hi+lo); exact fp32 GEMV against W.
// =====================================================================
__global__ void __launch_bounds__(256, 1)
comb_small(int src, int stage, const float* __restrict__ Wc, const float* __restrict__ Ws,
           const float* __restrict__ bc, const float* __restrict__ bs,
           float* __restrict__ root_out)
{
    __shared__ float sh[512];
    const int node = blockIdx.x, tid = threadIdx.x;
    const uint32_t* __restrict__ hp_in = src ? g_hpB : g_hpA;
    const float* __restrict__ c_in = src ? g_cB : g_cA;
    uint32_t* __restrict__ hp_out = src ? g_hpA : g_hpB;
    float* __restrict__ c_out = src ? g_cA : g_cB;

    if (stage == 1) {
        sh[tid] = unpackhl(hp_in[(size_t)(2 * node) * DH + tid]);
        __syncthreads();
        float gc = bc[256 + tid] + bs[256 + tid];
        float go = bc[512 + tid] + bs[512 + tid];
#pragma unroll 8
        for (int k = 0; k < DH; k++) {
            float h = sh[k];
            gc += h * Wc[(size_t)k * 768 + 256 + tid];
            go += h * Wc[(size_t)k * 768 + 512 + tid];
        }
        float cl = sigf(gc) * c_in[(size_t)(2 * node) * DH + tid];
        float hl = sigf(go) * tanhf(cl);
        g_cl[(size_t)node * DH + tid] = cl;
        if (root_out) root_out[tid] = hl;
        else g_hlp[(size_t)node * DH + tid] = packhl(hl);
    } else {
        sh[tid] = unpackhl(hp_in[(size_t)(2 * node + 1) * DH + tid]);
        sh[256 + tid] = unpackhl(g_hlp[(size_t)node * DH + tid]);
        __syncthreads();
        float gs = bc[tid] + bs[tid];
        float gc = bc[256 + tid] + bs[256 + tid];
        float go = bc[512 + tid] + bs[512 + tid];
#pragma unroll 4
        for (int k = 0; k < DH; k++) {
            float ho = sh[k], hs = sh[256 + k];
            gs += ho * Wc[(size_t)k * 768 + tid]       + hs * Ws[(size_t)k * 768 + tid];
            gc += ho * Wc[(size_t)k * 768 + 256 + tid] + hs * Ws[(size_t)k * 768 + 256 + tid];
            go += ho * Wc[(size_t)k * 768 + 512 + tid] + hs * Ws[(size_t)k * 768 + 512 + tid];
        }
        float cn = sigf(gc) * c_in[(size_t)(2 * node + 1) * DH + tid] +
                   sigf(gs) * g_cl[(size_t)node * DH + tid];
        float hn = sigf(go) * tanhf(cn);
        c_out[(size_t)node * DH + tid] = cn;
        hp_out[(size_t)node * DH + tid] = packhl(hn);
    }
}

// =====================================================================
extern "C" void kernel_launch(void* const* d_in, const int* in_sizes, int n_in,
                              void* d_out, int out_size)
{
    const int*   ids = (const int*)d_in[0];
    const float* emb = (const float*)d_in[1];
    const float* Wx  = (const float*)d_in[2];
    const float* bx  = (const float*)d_in[3];
    const float* Ws  = (const float*)d_in[4];
    const float* bs  = (const float*)d_in[5];
    const float* Wc  = (const float*)d_in[6];
    const float* bc  = (const float*)d_in[7];
    float* out = (float*)d_out;
    (void)in_sizes; (void)n_in; (void)out_size;

    // dynamic smem sizes (bytes)
    const int SM3 = (2 * 128 * APITCH + 2 * 2 * 3 * 64 * BPITCH + 192) * 4;  // MODE 0/2
    const int SM2 = (2 * 128 * APITCH + 2 * 2 * 2 * 64 * BPITCH + 128) * 4;  // MODE 1
    cudaFuncSetAttribute(tree_mma<0>, cudaFuncAttributeMaxDynamicSharedMemorySize, SM3);
    cudaFuncSetAttribute(tree_mma<1>, cudaFuncAttributeMaxDynamicSharedMemorySize, SM2);
    cudaFuncSetAttribute(tree_mma<2>, cudaFuncAttributeMaxDynamicSharedMemorySize, SM3);

    prep_wc<<<768, 256>>>(Wc, Ws);
    prep_wx<<<480, 256>>>(Wx);
    prep_emb<<<NLEAF * 320 / 256, 256>>>(ids, emb);

    // leaf
    tree_mma<0><<<dim3(NLEAF / 128, 4), 256, SM3>>>(0, bx, nullptr);

    int M = NLEAF;
    for (int l = 0; l < 14; l++) {
        int Mo = M >> 1;
        int src = l & 1;   // 0: read A / write B ; 1: read B / write A
        if (Mo >= 128) {
            dim3 grid(Mo / 128, 4);
            tree_mma<1><<<grid, 256, SM2>>>(src, bc, bs);
            tree_mma<2><<<grid, 256, SM3>>>(src, bc, bs);
        } else {
            comb_small<<<Mo, 256>>>(src, 1, Wc, Ws, bc, bs, nullptr);
            comb_small<<<Mo, 256>>>(src, 2, Wc, Ws, bc, bs, nullptr);
        }
        M = Mo;
    }
    // root: sibling = zeros -> stage-1 math; level-14 state is in A buffers
    comb_small<<<1, 256>>>(0, 1, Wc, Ws, bc, bs, out);
}